// round 11
// baseline (speedup 1.0000x reference)
#include <cuda_runtime.h>
#include <math.h>

#define BATCH 2
#define SEQ   2048
#define EMB   1024
#define NHEAD 16
#define HDIM  64
#define NEGF  1e30f

typedef unsigned long long u64;

// Scratch (allocation-free rule: __device__ globals)
__device__ float g_Q[BATCH * NHEAD * SEQ * HDIM];   // [B,H,S,D]
__device__ float g_K[BATCH * NHEAD * SEQ * HDIM];   // [B,H,S,D]
__device__ float g_V[BATCH * NHEAD * SEQ * HDIM];   // [B,H,S,D]
__device__ float g_A[BATCH * SEQ * EMB];            // [B,S,H*D]

// ---- packed f32x2 helpers -------------------------------------------------
__device__ __forceinline__ u64 pk2(float x, float y) {
    u64 r; asm("mov.b64 %0, {%1, %2};" : "=l"(r) : "f"(x), "f"(y)); return r;
}
__device__ __forceinline__ float2 up2(u64 v) {
    float2 f; asm("mov.b64 {%0, %1}, %2;" : "=f"(f.x), "=f"(f.y) : "l"(v)); return f;
}
#define FFMA2(C, A, B) asm("fma.rn.f32x2 %0, %1, %2, %0;" : "+l"(C) : "l"(A), "l"(B))
#define FMUL2(D, A, B) asm("mul.rn.f32x2 %0, %1, %2;" : "=l"(D) : "l"(A), "l"(B))

// union view: float4 register quad aliases 2 aligned u64 pairs (zero MOVs)
union F4 { float4 f; ulonglong2 u; };

// ============================================================================
// GEMM-NT 128x128x16, 256 threads, 8x8 per-thread tile (8x4 f32x2 pairs).
// A tile stored in smem as DUPLICATED pairs (a,a) -> broadcast operands load
// as register pairs with no packing MOVs. Single-buffered (fits 48KB static).
// C[m][n] = sum_k A[m][k] * B[n][k]
// ============================================================================

#define GEMM_BODY(APTR)                                                        \
    __shared__ u64  As2[16][128];                                              \
    __shared__ float Bs[16][132];                                              \
    const int tid = threadIdx.x;                                               \
    const int tx = tid & 15, ty = tid >> 4;                                    \
    const int bm = blockIdx.y * 128, bn = blockIdx.x * 128;                    \
    const int lrow = tid >> 2;                                                 \
    const int lc4  = (tid & 3) << 2;                                           \
    const int ty4 = ty * 4;                                                    \
    u64 acc2[8][4];                                                            \
    _Pragma("unroll")                                                          \
    for (int i = 0; i < 8; i++)                                                \
        _Pragma("unroll")                                                      \
        for (int j = 0; j < 4; j++) acc2[i][j] = 0ull;                         \
    const float* pA0 = (APTR) + (size_t)(bm + lrow) * EMB + lc4;               \
    const float* pA1 = (APTR) + (size_t)(bm + lrow + 64) * EMB + lc4;          \
    const float* pB0 = W + (size_t)(bn + lrow) * EMB + lc4;                    \
    const float* pB1 = W + (size_t)(bn + lrow + 64) * EMB + lc4;               \
    float4 ra0 = *(const float4*)pA0;                                          \
    float4 ra1 = *(const float4*)pA1;                                          \
    float4 rb0 = *(const float4*)pB0;                                          \
    float4 rb1 = *(const float4*)pB1;                                          \
    _Pragma("unroll 1")                                                        \
    for (int c = 0; c < EMB / 16; c++) {                                       \
        As2[lc4 + 0][lrow] = pk2(ra0.x, ra0.x);                                \
        As2[lc4 + 1][lrow] = pk2(ra0.y, ra0.y);                                \
        As2[lc4 + 2][lrow] = pk2(ra0.z, ra0.z);                                \
        As2[lc4 + 3][lrow] = pk2(ra0.w, ra0.w);                                \
        As2[lc4 + 0][lrow + 64] = pk2(ra1.x, ra1.x);                           \
        As2[lc4 + 1][lrow + 64] = pk2(ra1.y, ra1.y);                           \
        As2[lc4 + 2][lrow + 64] = pk2(ra1.z, ra1.z);                           \
        As2[lc4 + 3][lrow + 64] = pk2(ra1.w, ra1.w);                           \
        Bs[lc4 + 0][lrow] = rb0.x; Bs[lc4 + 1][lrow] = rb0.y;                  \
        Bs[lc4 + 2][lrow] = rb0.z; Bs[lc4 + 3][lrow] = rb0.w;                  \
        Bs[lc4 + 0][lrow + 64] = rb1.x; Bs[lc4 + 1][lrow + 64] = rb1.y;        \
        Bs[lc4 + 2][lrow + 64] = rb1.z; Bs[lc4 + 3][lrow + 64] = rb1.w;        \
        __syncthreads();                                                       \
        if (c + 1 < EMB / 16) {                                                \
            const int o = (c + 1) * 16;                                        \
            ra0 = *(const float4*)(pA0 + o);                                   \
            ra1 = *(const float4*)(pA1 + o);                                   \
            rb0 = *(const float4*)(pB0 + o);                                   \
            rb1 = *(const float4*)(pB1 + o);                                   \
        }                                                                      \
        _Pragma("unroll")                                                      \
        for (int k = 0; k < 16; k++) {                                         \
            ulonglong2 A01 = *(const ulonglong2*)&As2[k][ty4];                 \
            ulonglong2 A23 = *(const ulonglong2*)&As2[k][ty4 + 2];             \
            ulonglong2 A45 = *(const ulonglong2*)&As2[k][64 + ty4];            \
            ulonglong2 A67 = *(const ulonglong2*)&As2[k][64 + ty4 + 2];        \
            F4 b0, b1;                                                         \
            b0.f = *(const float4*)&Bs[k][tx * 4];                             \
            b1.f = *(const float4*)&Bs[k][64 + tx * 4];                        \
            u64 aa[8] = {A01.x, A01.y, A23.x, A23.y, A45.x, A45.y, A67.x, A67.y}; \
            _Pragma("unroll")                                                  \
            for (int i = 0; i < 8; i++) {                                      \
                FFMA2(acc2[i][0], aa[i], b0.u.x);                              \
                FFMA2(acc2[i][1], aa[i], b0.u.y);                              \
                FFMA2(acc2[i][2], aa[i], b1.u.x);                              \
                FFMA2(acc2[i][3], aa[i], b1.u.y);                              \
            }                                                                  \
        }                                                                      \
        __syncthreads();                                                       \
    }

// ---- QKV projection: X @ Wqkv^T + b, scatter to g_Q/g_K/g_V
__global__ __launch_bounds__(256)
void qkv_gemm_kernel(const float* __restrict__ X,
                     const float* __restrict__ W,
                     const float* __restrict__ bias)
{
    GEMM_BODY(X)
    #pragma unroll
    for (int i = 0; i < 8; i++) {
        int m = bm + ((i < 4) ? (ty * 4 + i) : (64 + ty * 4 + i - 4));
        int bb = m >> 11;
        int ss = m & (SEQ - 1);
        #pragma unroll
        for (int jp = 0; jp < 4; jp++) {
            int n = bn + ((jp < 2) ? (tx * 4 + jp * 2) : (64 + tx * 4 + (jp - 2) * 2));
            float2 cv = up2(acc2[i][jp]);
            cv.x += bias[n];
            cv.y += bias[n + 1];
            int w = n >> 10;
            int h = (n >> 6) & 15;
            int d = n & 63;
            float* dst = (w == 0) ? g_Q : (w == 1) ? g_K : g_V;
            *(float2*)&dst[(((size_t)(bb * NHEAD + h)) * SEQ + ss) * HDIM + d] = cv;
        }
    }
}

// ---- Output projection: g_A @ Wo^T + b -> out
__global__ __launch_bounds__(256)
void out_gemm_kernel(const float* __restrict__ W,
                     const float* __restrict__ bias,
                     float* __restrict__ out)
{
    GEMM_BODY(g_A)
    #pragma unroll
    for (int i = 0; i < 8; i++) {
        int m = bm + ((i < 4) ? (ty * 4 + i) : (64 + ty * 4 + i - 4));
        #pragma unroll
        for (int jp = 0; jp < 4; jp++) {
            int n = bn + ((jp < 2) ? (tx * 4 + jp * 2) : (64 + tx * 4 + (jp - 2) * 2));
            float2 cv = up2(acc2[i][jp]);
            cv.x += bias[n];
            cv.y += bias[n + 1];
            *(float2*)&out[(size_t)m * EMB + n] = cv;
        }
    }
}

// ============================================================================
// Flash attention, causal, fp32, f32x2, pack-free operands.
// Qs/Vs unpadded (broadcast / 2-way reads), Ks XOR-swizzled (granule ^ row),
// P stored duplicated as u64 pairs. Smem exactly 48KB. 2 block syncs/tile.
// ============================================================================
__global__ __launch_bounds__(256)
void attn_kernel(const float* __restrict__ ghost)
{
    __shared__ float Qs[64][64];
    __shared__ float Ks[32][64];
    __shared__ float Vs[32][64];
    __shared__ __align__(16) u64 Ss2[64][32];

    const int qi = blockIdx.x;          // 0..31
    const int bh = blockIdx.y;          // 0..31
    const int tid = threadIdx.x;
    const int tx = tid & 15, ty = tid >> 4;
    const int r0 = ty * 4;
    const int q0 = qi * 64;
    const int d0 = tx * 4;

    const float* Qb = g_Q + (size_t)bh * SEQ * HDIM;
    const float* Kb = g_K + (size_t)bh * SEQ * HDIM;
    const float* Vb = g_V + (size_t)bh * SEQ * HDIM;

    for (int i = tid; i < 64 * 16; i += 256) {
        int r = i >> 4, g = i & 15;
        *(float4*)&Qs[r][g << 2] = *(const float4*)&Qb[(size_t)(q0 + r) * HDIM + (g << 2)];
    }

    u64 acc2[4][2];
    float rm[4], rl[4];
    #pragma unroll
    for (int i = 0; i < 4; i++) {
        rm[i] = -NEGF; rl[i] = 0.f;
        acc2[i][0] = 0ull; acc2[i][1] = 0ull;
    }

    __syncthreads();

    const int nkt = 2 * qi + 2;
    #pragma unroll 1
    for (int kt = 0; kt < nkt; kt++) {
        const int k0 = kt * 32;
        for (int i = tid; i < 32 * 16; i += 256) {
            int r = i >> 4, g = i & 15;
            // K: swizzled granule (g ^ (r & 15)); V: plain
            *(float4*)&Ks[r][((g ^ (r & 15)) << 2)] =
                *(const float4*)&Kb[(size_t)(k0 + r) * HDIM + (g << 2)];
            *(float4*)&Vs[r][g << 2] =
                *(const float4*)&Vb[(size_t)(k0 + r) * HDIM + (g << 2)];
        }
        __syncthreads();

        // S = Q K^T (pairs along d, pack-free via union aliasing)
        u64 s2[4][2];
        #pragma unroll
        for (int i = 0; i < 4; i++) { s2[i][0] = 0ull; s2[i][1] = 0ull; }
        #pragma unroll
        for (int G = 0; G < 16; G++) {
            F4 k0v, k1v;
            k0v.f = *(const float4*)&Ks[tx][((G ^ tx) << 2)];
            k1v.f = *(const float4*)&Ks[tx + 16][((G ^ tx) << 2)];
            #pragma unroll
            for (int i = 0; i < 4; i++) {
                F4 qv;
                qv.f = *(const float4*)&Qs[r0 + i][G << 2];
                FFMA2(s2[i][0], qv.u.x, k0v.u.x);
                FFMA2(s2[i][0], qv.u.y, k0v.u.y);
                FFMA2(s2[i][1], qv.u.x, k1v.u.x);
                FFMA2(s2[i][1], qv.u.y, k1v.u.y);
            }
        }
        float s[4][2];
        #pragma unroll
        for (int i = 0; i < 4; i++) {
            float2 t0 = up2(s2[i][0]);
            float2 t1 = up2(s2[i][1]);
            s[i][0] = t0.x + t0.y;
            s[i][1] = t1.x + t1.y;
        }
        const bool need_mask = (kt >= 2 * qi);
        #pragma unroll
        for (int i = 0; i < 4; i++) {
            int qq = q0 + r0 + i;
            #pragma unroll
            for (int j = 0; j < 2; j++) {
                int kk = k0 + tx + 16 * j;
                float v = s[i][j] * 0.125f;
                if (need_mask && kk > qq) v = -NEGF;
                s[i][j] = v;
            }
        }

        // register online softmax; row group = 16 lanes (same ty)
        float sc[4];
        #pragma unroll
        for (int i = 0; i < 4; i++) {
            float t = fmaxf(s[i][0], s[i][1]);
            t = fmaxf(t, __shfl_xor_sync(0xffffffffu, t, 1));
            t = fmaxf(t, __shfl_xor_sync(0xffffffffu, t, 2));
            t = fmaxf(t, __shfl_xor_sync(0xffffffffu, t, 4));
            t = fmaxf(t, __shfl_xor_sync(0xffffffffu, t, 8));
            float mn = fmaxf(rm[i], t);
            sc[i] = __expf(rm[i] - mn);
            rm[i] = mn;
            float p0 = __expf(s[i][0] - mn);
            float p1 = __expf(s[i][1] - mn);
            float ps = p0 + p1;
            ps += __shfl_xor_sync(0xffffffffu, ps, 1);
            ps += __shfl_xor_sync(0xffffffffu, ps, 2);
            ps += __shfl_xor_sync(0xffffffffu, ps, 4);
            ps += __shfl_xor_sync(0xffffffffu, ps, 8);
            rl[i] = rl[i] * sc[i] + ps;
            Ss2[r0 + i][tx]      = pk2(p0, p0);   // duplicated pairs
            Ss2[r0 + i][tx + 16] = pk2(p1, p1);
        }
        __syncwarp();   // Ss2 rows are warp-private: no block barrier needed

        // O = O*sc + P @ V (pack-free: P pre-duplicated, V pairs aliased)
        #pragma unroll
        for (int i = 0; i < 4; i++) {
            u64 scp = pk2(sc[i], sc[i]);
            FMUL2(acc2[i][0], acc2[i][0], scp);
            FMUL2(acc2[i][1], acc2[i][1], scp);
        }
        #pragma unroll
        for (int c = 0; c < 32; c += 2) {
            F4 v0, v1;
            v0.f = *(const float4*)&Vs[c][d0];
            v1.f = *(const float4*)&Vs[c + 1][d0];
            #pragma unroll
            for (int i = 0; i < 4; i++) {
                ulonglong2 P = *(const ulonglong2*)&Ss2[r0 + i][c];
                FFMA2(acc2[i][0], P.x, v0.u.x);
                FFMA2(acc2[i][1], P.x, v0.u.y);
                FFMA2(acc2[i][0], P.y, v1.u.x);
                FFMA2(acc2[i][1], P.y, v1.u.y);
            }
        }
        __syncthreads();
    }

    // epilogue: A[b, q, h*64 + d] = acc / (l + ghost[h])
    const int bb = bh >> 4, hh = bh & 15;
    const float gh = ghost[hh];
    #pragma unroll
    for (int i = 0; i < 4; i++) {
        int qq = q0 + r0 + i;
        float inv = 1.0f / (rl[i] + gh);
        float2 lo = up2(acc2[i][0]);
        float2 hi = up2(acc2[i][1]);
        float* dst = g_A + ((size_t)(bb * SEQ + qq)) * EMB + hh * HDIM + tx * 4;
        dst[0] = lo.x * inv;
        dst[1] = lo.y * inv;
        dst[2] = hi.x * inv;
        dst[3] = hi.y * inv;
    }
}

// ============================================================================
extern "C" void kernel_launch(void* const* d_in, const int* in_sizes, int n_in,
                              void* d_out, int out_size)
{
    const float* X      = (const float*)d_in[0];  // [2,2048,1024]
    const float* Wqkv_w = (const float*)d_in[1];  // [3072,1024]
    const float* Wqkv_b = (const float*)d_in[2];  // [3072]
    const float* Wo_w   = (const float*)d_in[3];  // [1024,1024]
    const float* Wo_b   = (const float*)d_in[4];  // [1024]
    const float* ghost  = (const float*)d_in[5];  // [16]
    float* out = (float*)d_out;

    dim3 g1(3072 / 128, (BATCH * SEQ) / 128);     // 24 x 32
    qkv_gemm_kernel<<<g1, 256>>>(X, Wqkv_w, Wqkv_b);

    dim3 g2(SEQ / 64, BATCH * NHEAD);             // 32 x 32
    attn_kernel<<<g2, 256>>>(ghost);

    dim3 g3(EMB / 128, (BATCH * SEQ) / 128);      // 8 x 32
    out_gemm_kernel<<<g3, 256>>>(Wo_w, Wo_b, out);
}

// round 13
// speedup vs baseline: 1.0020x; 1.0020x over previous
#include <cuda_runtime.h>
#include <math.h>

#define BATCH 2
#define SEQ   2048
#define EMB   1024
#define NHEAD 16
#define HDIM  64
#define NEGF  1e30f

typedef unsigned long long u64;

// Scratch (allocation-free rule: __device__ globals)
__device__ float g_Q[BATCH * NHEAD * SEQ * HDIM];   // [B,H,S,D]
__device__ float g_K[BATCH * NHEAD * SEQ * HDIM];   // [B,H,S,D]
__device__ float g_V[BATCH * NHEAD * SEQ * HDIM];   // [B,H,S,D]
__device__ float g_A[BATCH * SEQ * EMB];            // [B,S,H*D]

// ---- packed f32x2 helpers -------------------------------------------------
__device__ __forceinline__ u64 pk2(float x, float y) {
    u64 r; asm("mov.b64 %0, {%1, %2};" : "=l"(r) : "f"(x), "f"(y)); return r;
}
__device__ __forceinline__ float2 up2(u64 v) {
    float2 f; asm("mov.b64 {%0, %1}, %2;" : "=f"(f.x), "=f"(f.y) : "l"(v)); return f;
}
#define FFMA2(C, A, B) asm("fma.rn.f32x2 %0, %1, %2, %0;" : "+l"(C) : "l"(A), "l"(B))
#define FMUL2(D, A, B) asm("mul.rn.f32x2 %0, %1, %2;" : "=l"(D) : "l"(A), "l"(B))

// union view: float4 register quad aliases 2 aligned u64 pairs (zero MOVs)
union F4 { float4 f; ulonglong2 u; };

// ============================================================================
// GEMM-NT 128x128x16, 256 threads, 8x8 per-thread tile (8x4 f32x2 pairs).
// A tile stored in smem as DUPLICATED pairs (a,a) -> broadcast operands load
// as register pairs with no packing MOVs. Single-buffered (fits 48KB static).
// C[m][n] = sum_k A[m][k] * B[n][k]
// ============================================================================

#define GEMM_BODY(APTR)                                                        \
    __shared__ u64  As2[16][128];                                              \
    __shared__ float Bs[16][132];                                              \
    const int tid = threadIdx.x;                                               \
    const int tx = tid & 15, ty = tid >> 4;                                    \
    const int bm = blockIdx.y * 128, bn = blockIdx.x * 128;                    \
    const int lrow = tid >> 2;                                                 \
    const int lc4  = (tid & 3) << 2;                                           \
    const int ty4 = ty * 4;                                                    \
    u64 acc2[8][4];                                                            \
    _Pragma("unroll")                                                          \
    for (int i = 0; i < 8; i++)                                                \
        _Pragma("unroll")                                                      \
        for (int j = 0; j < 4; j++) acc2[i][j] = 0ull;                         \
    const float* pA0 = (APTR) + (size_t)(bm + lrow) * EMB + lc4;               \
    const float* pA1 = (APTR) + (size_t)(bm + lrow + 64) * EMB + lc4;          \
    const float* pB0 = W + (size_t)(bn + lrow) * EMB + lc4;                    \
    const float* pB1 = W + (size_t)(bn + lrow + 64) * EMB + lc4;               \
    float4 ra0 = *(const float4*)pA0;                                          \
    float4 ra1 = *(const float4*)pA1;                                          \
    float4 rb0 = *(const float4*)pB0;                                          \
    float4 rb1 = *(const float4*)pB1;                                          \
    _Pragma("unroll 1")                                                        \
    for (int c = 0; c < EMB / 16; c++) {                                       \
        As2[lc4 + 0][lrow] = pk2(ra0.x, ra0.x);                                \
        As2[lc4 + 1][lrow] = pk2(ra0.y, ra0.y);                                \
        As2[lc4 + 2][lrow] = pk2(ra0.z, ra0.z);                                \
        As2[lc4 + 3][lrow] = pk2(ra0.w, ra0.w);                                \
        As2[lc4 + 0][lrow + 64] = pk2(ra1.x, ra1.x);                           \
        As2[lc4 + 1][lrow + 64] = pk2(ra1.y, ra1.y);                           \
        As2[lc4 + 2][lrow + 64] = pk2(ra1.z, ra1.z);                           \
        As2[lc4 + 3][lrow + 64] = pk2(ra1.w, ra1.w);                           \
        Bs[lc4 + 0][lrow] = rb0.x; Bs[lc4 + 1][lrow] = rb0.y;                  \
        Bs[lc4 + 2][lrow] = rb0.z; Bs[lc4 + 3][lrow] = rb0.w;                  \
        Bs[lc4 + 0][lrow + 64] = rb1.x; Bs[lc4 + 1][lrow + 64] = rb1.y;        \
        Bs[lc4 + 2][lrow + 64] = rb1.z; Bs[lc4 + 3][lrow + 64] = rb1.w;        \
        __syncthreads();                                                       \
        if (c + 1 < EMB / 16) {                                                \
            const int o = (c + 1) * 16;                                        \
            ra0 = *(const float4*)(pA0 + o);                                   \
            ra1 = *(const float4*)(pA1 + o);                                   \
            rb0 = *(const float4*)(pB0 + o);                                   \
            rb1 = *(const float4*)(pB1 + o);                                   \
        }                                                                      \
        _Pragma("unroll")                                                      \
        for (int k = 0; k < 16; k++) {                                         \
            ulonglong2 A01 = *(const ulonglong2*)&As2[k][ty4];                 \
            ulonglong2 A23 = *(const ulonglong2*)&As2[k][ty4 + 2];             \
            ulonglong2 A45 = *(const ulonglong2*)&As2[k][64 + ty4];            \
            ulonglong2 A67 = *(const ulonglong2*)&As2[k][64 + ty4 + 2];        \
            F4 b0, b1;                                                         \
            b0.f = *(const float4*)&Bs[k][tx * 4];                             \
            b1.f = *(const float4*)&Bs[k][64 + tx * 4];                        \
            u64 aa[8] = {A01.x, A01.y, A23.x, A23.y, A45.x, A45.y, A67.x, A67.y}; \
            _Pragma("unroll")                                                  \
            for (int i = 0; i < 8; i++) {                                      \
                FFMA2(acc2[i][0], aa[i], b0.u.x);                              \
                FFMA2(acc2[i][1], aa[i], b0.u.y);                              \
                FFMA2(acc2[i][2], aa[i], b1.u.x);                              \
                FFMA2(acc2[i][3], aa[i], b1.u.y);                              \
            }                                                                  \
        }                                                                      \
        __syncthreads();                                                       \
    }

// ---- QKV projection: X @ Wqkv^T + b, scatter to g_Q/g_K/g_V
__global__ __launch_bounds__(256)
void qkv_gemm_kernel(const float* __restrict__ X,
                     const float* __restrict__ W,
                     const float* __restrict__ bias)
{
    GEMM_BODY(X)
    #pragma unroll
    for (int i = 0; i < 8; i++) {
        int m = bm + ((i < 4) ? (ty * 4 + i) : (64 + ty * 4 + i - 4));
        int bb = m >> 11;
        int ss = m & (SEQ - 1);
        #pragma unroll
        for (int jp = 0; jp < 4; jp++) {
            int n = bn + ((jp < 2) ? (tx * 4 + jp * 2) : (64 + tx * 4 + (jp - 2) * 2));
            float2 cv = up2(acc2[i][jp]);
            cv.x += bias[n];
            cv.y += bias[n + 1];
            int w = n >> 10;
            int h = (n >> 6) & 15;
            int d = n & 63;
            float* dst = (w == 0) ? g_Q : (w == 1) ? g_K : g_V;
            *(float2*)&dst[(((size_t)(bb * NHEAD + h)) * SEQ + ss) * HDIM + d] = cv;
        }
    }
}

// ---- Output projection: g_A @ Wo^T + b -> out
__global__ __launch_bounds__(256)
void out_gemm_kernel(const float* __restrict__ W,
                     const float* __restrict__ bias,
                     float* __restrict__ out)
{
    GEMM_BODY(g_A)
    #pragma unroll
    for (int i = 0; i < 8; i++) {
        int m = bm + ((i < 4) ? (ty * 4 + i) : (64 + ty * 4 + i - 4));
        #pragma unroll
        for (int jp = 0; jp < 4; jp++) {
            int n = bn + ((jp < 2) ? (tx * 4 + jp * 2) : (64 + tx * 4 + (jp - 2) * 2));
            float2 cv = up2(acc2[i][jp]);
            cv.x += bias[n];
            cv.y += bias[n + 1];
            *(float2*)&out[(size_t)m * EMB + n] = cv;
        }
    }
}

// ============================================================================
// Flash attention, causal, fp32, f32x2, pack-free operands.
// Qs/Vs unpadded (broadcast / 2-way reads), Ks XOR-swizzled (granule ^ row),
// P stored duplicated as u64 pairs. Smem exactly 48KB. 2 block syncs/tile.
// ============================================================================
__global__ __launch_bounds__(256)
void attn_kernel(const float* __restrict__ ghost)
{
    __shared__ float Qs[64][64];
    __shared__ float Ks[32][64];
    __shared__ float Vs[32][64];
    __shared__ __align__(16) u64 Ss2[64][32];

    const int qi = blockIdx.x;          // 0..31
    const int bh = blockIdx.y;          // 0..31
    const int tid = threadIdx.x;
    const int tx = tid & 15, ty = tid >> 4;
    const int r0 = ty * 4;
    const int q0 = qi * 64;
    const int d0 = tx * 4;

    const float* Qb = g_Q + (size_t)bh * SEQ * HDIM;
    const float* Kb = g_K + (size_t)bh * SEQ * HDIM;
    const float* Vb = g_V + (size_t)bh * SEQ * HDIM;

    for (int i = tid; i < 64 * 16; i += 256) {
        int r = i >> 4, g = i & 15;
        *(float4*)&Qs[r][g << 2] = *(const float4*)&Qb[(size_t)(q0 + r) * HDIM + (g << 2)];
    }

    u64 acc2[4][2];
    float rm[4], rl[4];
    #pragma unroll
    for (int i = 0; i < 4; i++) {
        rm[i] = -NEGF; rl[i] = 0.f;
        acc2[i][0] = 0ull; acc2[i][1] = 0ull;
    }

    __syncthreads();

    const int nkt = 2 * qi + 2;
    #pragma unroll 1
    for (int kt = 0; kt < nkt; kt++) {
        const int k0 = kt * 32;
        for (int i = tid; i < 32 * 16; i += 256) {
            int r = i >> 4, g = i & 15;
            // K: swizzled granule (g ^ (r & 15)); V: plain
            *(float4*)&Ks[r][((g ^ (r & 15)) << 2)] =
                *(const float4*)&Kb[(size_t)(k0 + r) * HDIM + (g << 2)];
            *(float4*)&Vs[r][g << 2] =
                *(const float4*)&Vb[(size_t)(k0 + r) * HDIM + (g << 2)];
        }
        __syncthreads();

        // S = Q K^T (pairs along d, pack-free via union aliasing)
        u64 s2[4][2];
        #pragma unroll
        for (int i = 0; i < 4; i++) { s2[i][0] = 0ull; s2[i][1] = 0ull; }
        #pragma unroll
        for (int G = 0; G < 16; G++) {
            F4 k0v, k1v;
            k0v.f = *(const float4*)&Ks[tx][((G ^ tx) << 2)];
            k1v.f = *(const float4*)&Ks[tx + 16][((G ^ tx) << 2)];
            #pragma unroll
            for (int i = 0; i < 4; i++) {
                F4 qv;
                qv.f = *(const float4*)&Qs[r0 + i][G << 2];
                FFMA2(s2[i][0], qv.u.x, k0v.u.x);
                FFMA2(s2[i][0], qv.u.y, k0v.u.y);
                FFMA2(s2[i][1], qv.u.x, k1v.u.x);
                FFMA2(s2[i][1], qv.u.y, k1v.u.y);
            }
        }
        float s[4][2];
        #pragma unroll
        for (int i = 0; i < 4; i++) {
            float2 t0 = up2(s2[i][0]);
            float2 t1 = up2(s2[i][1]);
            s[i][0] = t0.x + t0.y;
            s[i][1] = t1.x + t1.y;
        }
        const bool need_mask = (kt >= 2 * qi);
        #pragma unroll
        for (int i = 0; i < 4; i++) {
            int qq = q0 + r0 + i;
            #pragma unroll
            for (int j = 0; j < 2; j++) {
                int kk = k0 + tx + 16 * j;
                float v = s[i][j] * 0.125f;
                if (need_mask && kk > qq) v = -NEGF;
                s[i][j] = v;
            }
        }

        // register online softmax; row group = 16 lanes (same ty)
        float sc[4];
        #pragma unroll
        for (int i = 0; i < 4; i++) {
            float t = fmaxf(s[i][0], s[i][1]);
            t = fmaxf(t, __shfl_xor_sync(0xffffffffu, t, 1));
            t = fmaxf(t, __shfl_xor_sync(0xffffffffu, t, 2));
            t = fmaxf(t, __shfl_xor_sync(0xffffffffu, t, 4));
            t = fmaxf(t, __shfl_xor_sync(0xffffffffu, t, 8));
            float mn = fmaxf(rm[i], t);
            sc[i] = __expf(rm[i] - mn);
            rm[i] = mn;
            float p0 = __expf(s[i][0] - mn);
            float p1 = __expf(s[i][1] - mn);
            float ps = p0 + p1;
            ps += __shfl_xor_sync(0xffffffffu, ps, 1);
            ps += __shfl_xor_sync(0xffffffffu, ps, 2);
            ps += __shfl_xor_sync(0xffffffffu, ps, 4);
            ps += __shfl_xor_sync(0xffffffffu, ps, 8);
            rl[i] = rl[i] * sc[i] + ps;
            Ss2[r0 + i][tx]      = pk2(p0, p0);   // duplicated pairs
            Ss2[r0 + i][tx + 16] = pk2(p1, p1);
        }
        __syncwarp();   // Ss2 rows are warp-private: no block barrier needed

        // O = O*sc + P @ V (pack-free: P pre-duplicated, V pairs aliased)
        #pragma unroll
        for (int i = 0; i < 4; i++) {
            u64 scp = pk2(sc[i], sc[i]);
            FMUL2(acc2[i][0], acc2[i][0], scp);
            FMUL2(acc2[i][1], acc2[i][1], scp);
        }
        #pragma unroll
        for (int c = 0; c < 32; c += 2) {
            F4 v0, v1;
            v0.f = *(const float4*)&Vs[c][d0];
            v1.f = *(const float4*)&Vs[c + 1][d0];
            #pragma unroll
            for (int i = 0; i < 4; i++) {
                ulonglong2 P = *(const ulonglong2*)&Ss2[r0 + i][c];
                FFMA2(acc2[i][0], P.x, v0.u.x);
                FFMA2(acc2[i][1], P.x, v0.u.y);
                FFMA2(acc2[i][0], P.y, v1.u.x);
                FFMA2(acc2[i][1], P.y, v1.u.y);
            }
        }
        __syncthreads();
    }

    // epilogue: A[b, q, h*64 + d] = acc / (l + ghost[h])
    const int bb = bh >> 4, hh = bh & 15;
    const float gh = ghost[hh];
    #pragma unroll
    for (int i = 0; i < 4; i++) {
        int qq = q0 + r0 + i;
        float inv = 1.0f / (rl[i] + gh);
        float2 lo = up2(acc2[i][0]);
        float2 hi = up2(acc2[i][1]);
        float* dst = g_A + ((size_t)(bb * SEQ + qq)) * EMB + hh * HDIM + tx * 4;
        dst[0] = lo.x * inv;
        dst[1] = lo.y * inv;
        dst[2] = hi.x * inv;
        dst[3] = hi.y * inv;
    }
}

// ============================================================================
extern "C" void kernel_launch(void* const* d_in, const int* in_sizes, int n_in,
                              void* d_out, int out_size)
{
    const float* X      = (const float*)d_in[0];  // [2,2048,1024]
    const float* Wqkv_w = (const float*)d_in[1];  // [3072,1024]
    const float* Wqkv_b = (const float*)d_in[2];  // [3072]
    const float* Wo_w   = (const float*)d_in[3];  // [1024,1024]
    const float* Wo_b   = (const float*)d_in[4];  // [1024]
    const float* ghost  = (const float*)d_in[5];  // [16]
    float* out = (float*)d_out;

    dim3 g1(3072 / 128, (BATCH * SEQ) / 128);     // 24 x 32
    qkv_gemm_kernel<<<g1, 256>>>(X, Wqkv_w, Wqkv_b);

    dim3 g2(SEQ / 64, BATCH * NHEAD);             // 32 x 32
    attn_kernel<<<g2, 256>>>(ghost);

    dim3 g3(EMB / 128, (BATCH * SEQ) / 128);      // 8 x 32
    out_gemm_kernel<<<g3, 256>>>(Wo_w, Wo_b, out);
}